// round 16
// baseline (speedup 1.0000x reference)
#include <cuda_runtime.h>
#include <cuda_fp16.h>
#include <cstdint>

#define E_TOT      100000
#define NCHUNK     43           /* superchunks of K=192; 43*192 = 8256 = 64*128+64 */
#define NWTILE     65           /* W tiles of K=128 (incl. bias tile 64) */
#define B_TILE     16384
#define W_RING     5
#define NTILES     782          /* ceil(100000/128) */
#define NTHREADS   288          /* 8 producer warps + 1 issuer warp */

/* ---- tcgen05-path smem layout (relative to 1024-aligned base) ---- */
#define SM_B       0            /* 5 x 16384 = 81920 : W tile ring (TMA) */
#define SM_V       81920        /* 128 rows x 132 B fp16 vert = 16896    */
#define SM_TPTR    98816
#define SM_MB_D    98832        /* 2 x 8B : mma committed (A-buf gate) */
#define SM_MB_A    98848        /* 2 x 8B : A-buf full (count 8)       */
#define SM_MB_B    98864        /* 5 x 8B : W-tile full (TMA)          */
#define SM_END     98904

#define SMEM_DYN   (SM_END + 1024)   /* ~99.9KB/CTA -> 2 CTAs/SM */

/* TMEM column map (alloc 256): D = [0,64), A bufs 96 cols at 64 / 160 */
#define TM_D       0
#define TM_A       64

/* last chunk j=42: slot 42&1=0, parity (42>>1)&1=1 */
#define LAST_S     0
#define LAST_P     1

/* ---- fallback-path smem layout (compile-only on plain sm_103 pass) ---- */
#define FB_X       0
#define FB_V       67584
#define FB_B       101376
#define FB_S       168960

/* does this device pass have tcgen05 (arch-specific sm_103a/sm_100a)? */
#if !defined(__CUDA_ARCH__)
#  define TCPATH 1   /* host pass: parse the tcgen05 branch (not codegen'd) */
#elif defined(__CUDA_ARCH_FEAT_SM103_ALL) || defined(__CUDA_ARCH_FEAT_SM100_ALL) || \
      defined(__CUDA_ARCH_FEAT_SM101_ALL) || defined(__CUDA_ARCH_SPECIFIC__)
#  define TCPATH 1
#else
#  define TCPATH 0
#endif

/* pre-swizzled fp16 W' image: 65 tiles of [64 n x 128 k] blocked SW128 */
__device__ __align__(16) unsigned char g_Wimg[NWTILE * B_TILE];

/* ---------------- generic helpers ---------------- */

__device__ __forceinline__ uint32_t sw128(uint32_t x) { return x ^ ((x >> 3) & 0x70u); }

__device__ __forceinline__ uint32_t smem_u32(const void* p) {
    uint32_t a;
    asm("{ .reg .u64 t; cvta.to.shared.u64 t, %1; cvt.u32.u64 %0, t; }" : "=r"(a) : "l"(p));
    return a;
}

/* pack two f32 -> f16x2; 'lo' lands in the low (memory-first) half */
__device__ __forceinline__ uint32_t pack_h2(float lo, float hi) {
    uint32_t r;
    asm("cvt.rn.f16x2.f32 %0, %1, %2;" : "=r"(r) : "f"(hi), "f"(lo));
    return r;
}

__device__ __forceinline__ uint32_t hmul2(uint32_t a, uint32_t b) {
    uint32_t r;
    asm("mul.rn.f16x2 %0, %1, %2;" : "=r"(r) : "r"(a), "r"(b));
    return r;
}

__device__ __forceinline__ void sts32(uint32_t addr, uint32_t a) {
    asm volatile("st.shared.b32 [%0], %1;" :: "r"(addr), "r"(a) : "memory");
}
__device__ __forceinline__ uint32_t lds32(uint32_t addr) {
    uint32_t v;
    asm volatile("ld.shared.b32 %0, [%1];" : "=r"(v) : "r"(addr));
    return v;
}

__device__ __forceinline__ void mbar_wait(uint32_t mbar, uint32_t parity) {
    asm volatile(
        "{\n\t.reg .pred P;\n\tWL_%=:\n\t"
        "mbarrier.try_wait.parity.acquire.cta.shared::cta.b64 P, [%0], %1, 0x989680;\n\t"
        "@P bra.uni WD_%=;\n\tbra.uni WL_%=;\n\tWD_%=:\n\t}"
        :: "r"(mbar), "r"(parity) : "memory");
}

/* relaxed variant: ONLY for waits whose post-wait accesses to the protected
   data are async-proxy (tcgen05.st / TMA); tcgen05.fence::after follows. */
__device__ __forceinline__ void mbar_wait_relaxed(uint32_t mbar, uint32_t parity) {
    asm volatile(
        "{\n\t.reg .pred P;\n\tWL_%=:\n\t"
        "mbarrier.try_wait.parity.relaxed.cta.shared::cta.b64 P, [%0], %1, 0x989680;\n\t"
        "@P bra.uni WD_%=;\n\tbra.uni WL_%=;\n\tWD_%=:\n\t}"
        :: "r"(mbar), "r"(parity) : "memory");
}

#if TCPATH
/* store 32 b32 to 32 consecutive TMEM columns (warp-collective) */
__device__ __forceinline__ void sttm_x32(uint32_t addr, const uint32_t* t) {
    asm volatile(
        "tcgen05.st.sync.aligned.32x32b.x32.b32 [%0], "
        "{%1, %2, %3, %4, %5, %6, %7, %8, "
        " %9, %10, %11, %12, %13, %14, %15, %16, "
        " %17, %18, %19, %20, %21, %22, %23, %24, "
        " %25, %26, %27, %28, %29, %30, %31, %32};"
        :: "r"(addr),
           "r"(t[0]),  "r"(t[1]),  "r"(t[2]),  "r"(t[3]),
           "r"(t[4]),  "r"(t[5]),  "r"(t[6]),  "r"(t[7]),
           "r"(t[8]),  "r"(t[9]),  "r"(t[10]), "r"(t[11]),
           "r"(t[12]), "r"(t[13]), "r"(t[14]), "r"(t[15]),
           "r"(t[16]), "r"(t[17]), "r"(t[18]), "r"(t[19]),
           "r"(t[20]), "r"(t[21]), "r"(t[22]), "r"(t[23]),
           "r"(t[24]), "r"(t[25]), "r"(t[26]), "r"(t[27]),
           "r"(t[28]), "r"(t[29]), "r"(t[30]), "r"(t[31])
        : "memory");
}

__device__ __forceinline__ void tma_w(uint32_t dst, const unsigned char* src, uint32_t mbar) {
    asm volatile("mbarrier.arrive.expect_tx.shared.b64 _, [%0], %1;"
                 :: "r"(mbar), "r"((uint32_t)B_TILE) : "memory");
    asm volatile("cp.async.bulk.shared::cta.global.mbarrier::complete_tx::bytes [%0], [%1], %2, [%3];"
                 :: "r"(dst), "l"(src), "r"((uint32_t)B_TILE), "r"(mbar) : "memory");
}
#endif

/* ---------------- prep kernel: pre-swizzled fp16 W' image ---------------- */
/* tile c<64: Wc[n,k] = W[n*64+c, k]; tile 64: Wc[n,k] = (k<64)? b[n*64+k] : 0 */
__global__ void prep_w(const float* __restrict__ W, const float* __restrict__ b) {
    uint32_t gid = blockIdx.x * 256u + threadIdx.x;      /* 0 .. 266239 */
    uint32_t c  = gid >> 12;
    uint32_t r  = gid & 4095u;
    uint32_t n  = r >> 6;
    uint32_t k  = (r & 63u) * 2u;
    float w0, w1;
    if (c < 64u) {
        const float* s = W + ((n * 64u + c) * 128u + k);
        w0 = s[0]; w1 = s[1];
    } else if (k < 64u) {
        w0 = b[n * 64u + k]; w1 = b[n * 64u + k + 1u];
    } else {
        w0 = 0.f; w1 = 0.f;
    }
    uint32_t off = ((n >> 3) + (k >> 6) * 8u) * 1024u + (n & 7u) * 128u + (k & 63u) * 2u;
    *(uint32_t*)(g_Wimg + c * B_TILE + sw128(off)) = pack_h2(w0, w1);
}

/* ---------------- main kernel ---------------- */
__global__ void __launch_bounds__(NTHREADS, 2)
edge_msg_main(const float* __restrict__ vert,
              const float* __restrict__ xedges,
              const float* __restrict__ Wg,
              const float* __restrict__ bg,
              float* __restrict__ out)
{
    extern __shared__ unsigned char smem_raw[];
    const uint32_t raw  = smem_u32(smem_raw);
    const uint32_t base = (raw + 1023u) & ~1023u;
    unsigned char* sb   = smem_raw + (base - raw);

    const int tid  = threadIdx.x;
    const int tb   = blockIdx.x * 128;

#if TCPATH
    /* ========== tcgen05 path: K=192 superchunks (43), A ring depth 2 in TMEM,
       W tile-ring depth 5 (TMA), deferred wait::st, warp-3 B-gate with tile
       cursor, warp-6 W refills, lean issuer warp ===== */
    const int wid    = tid >> 5;
    const int lane   = tid & 31;
    const bool prod  = (tid < 256);
    const int wg     = (tid >> 7) & 1; /* producers: edge K-half owner (0/1) */
    const int wg_tid = tid & 127;
    const int r      = wg_tid;         /* owned A row (M index) */

    (void)Wg; (void)bg; (void)sb;

    if (tid == 0) {
        #pragma unroll
        for (int i = 0; i < 2; i++) {
            asm volatile("mbarrier.init.shared.b64 [%0], 1;" :: "r"(base + SM_MB_D + i * 8) : "memory");
            asm volatile("mbarrier.init.shared.b64 [%0], 8;" :: "r"(base + SM_MB_A + i * 8) : "memory");
        }
        #pragma unroll
        for (int i = 0; i < W_RING; i++)
            asm volatile("mbarrier.init.shared.b64 [%0], 1;" :: "r"(base + SM_MB_B + i * 8) : "memory");
    }
    if (wid == 0) {
        asm volatile("tcgen05.alloc.cta_group::1.sync.aligned.shared::cta.b32 [%0], 256;"
                     :: "r"(base + SM_TPTR) : "memory");
        asm volatile("tcgen05.relinquish_alloc_permit.cta_group::1.sync.aligned;");
    }
    __syncthreads();
    uint32_t tmem;
    asm volatile("ld.shared.b32 %0, [%1];" : "=r"(tmem) : "r"(base + SM_TPTR));

    bool lane_elect = false;
    {
        uint32_t p;
        asm volatile("{\n\t.reg .pred P;\n\telect.sync _|P, 0xFFFFFFFF;\n\tselp.b32 %0, 1, 0, P;\n\t}" : "=r"(p));
        lane_elect = (p != 0);
    }
    const bool is_issuer = (wid == 8) && lane_elect;
    const bool bgate     = (wid == 3);   /* producer warp that gates on W residency */
    const bool wfill     = (wid == 6);   /* producer warp that issues W refills     */

    /* prefetch W tiles 0,1,2 via TMA (issuer) */
    if (is_issuer) {
        #pragma unroll
        for (int t0 = 0; t0 < 3; t0++)
            tma_w(base + SM_B + (uint32_t)t0 * B_TILE, g_Wimg + (size_t)t0 * B_TILE,
                  base + SM_MB_B + (uint32_t)t0 * 8);
    }

    int e = tb + r; if (e >= E_TOT) e = E_TOT - 1;

    /* producers: stage vertices as fp16 (row stride 132 B) + edge half-row regs */
    const uint32_t vb    = base + SM_V;
    const uint32_t vrow  = vb + (uint32_t)(r * 132);
    uint32_t xh[32];
    uint32_t warp_off = 0;
    if (prod) {
        const float4* vp = (const float4*)(vert + (size_t)e * 64 + wg * 32);
        uint32_t dst = vrow + (uint32_t)(wg * 64);
        #pragma unroll
        for (int i = 0; i < 8; i++) {
            float4 v = vp[i];
            sts32(dst + (uint32_t)(i * 8),     pack_h2(v.x, v.y));
            sts32(dst + (uint32_t)(i * 8 + 4), pack_h2(v.z, v.w));
        }
        const float4* xp = (const float4*)(xedges + (size_t)e * 128 + wg * 64);
        #pragma unroll
        for (int i = 0; i < 16; i++) {
            float4 v = xp[i];
            xh[i * 2 + 0] = pack_h2(v.x, v.y);
            xh[i * 2 + 1] = pack_h2(v.z, v.w);
        }
        warp_off = ((uint32_t)(wg_tid >> 5)) << 21;
    }
    __syncthreads();   /* vertices staged, mbarriers live, TMEM ptr read */

    /* smem desc base: SW128, version=1, SBO=64, LBO=1 */
    const uint64_t DBASE = (uint64_t(2) << 61) | (uint64_t(1) << 46) |
                           (uint64_t(64) << 32) | (uint64_t(1) << 16);

    if (prod) {
        /* ---------------- producer warps ---------------- */
        int bt = 0;         /* warp-3 W-tile cursor */
        int wnext = 3;      /* warp-6 next W tile to load */
        for (int j = 0; j < NCHUNK; j++) {
            const uint32_t abase = tmem + TM_A + (uint32_t)(j & 1) * 96u + warp_off;

            /* A-buf reuse gate: commit of chunk j-2 (same slot, prev phase) */
            if (j >= 2) {
                mbar_wait_relaxed(base + SM_MB_D + (j & 1) * 8, (uint32_t)(((j >> 1) & 1) ^ 1));
                asm volatile("tcgen05.fence::after_thread_sync;" ::: "memory");
            }

            /* warp 6: refill W tiles whose ring slot is free.
               Free bound: slot of tile t held tile t-5, last read by chunk
               floor((2(t-5)+1)/3) <= j-2  <=>  t <= (3j-5)/2 + 5.
               For j<2 only tiles 3,4 (virgin slots) are allowed. */
            if (wfill && lane_elect) {
                int lim = (j >= 2) ? (((3 * j - 5) >> 1) + 5) : 4;
                while (wnext < NWTILE && wnext <= lim) {
                    uint32_t ws = (uint32_t)(wnext % W_RING);
                    tma_w(base + SM_B + ws * B_TILE,
                          g_Wimg + (size_t)wnext * B_TILE,
                          base + SM_MB_B + ws * 8);
                    wnext++;
                }
            }

            /* sub-block ownership: m = 3j+s has edge-half (m&1).
               group wg==(j&1) owns s=0 and s=2; the other group owns s=1. */
            const bool two = (wg == (j & 1));
            const int  sA  = two ? 0 : 1;
            const int  mA  = 3 * j + sA;

            /* compute first owned sub-block while STTM(j-1) drains */
            uint32_t t[32];
            {
                uint32_t w  = lds32(vrow + (uint32_t)((mA >> 2) << 2));
                uint32_t ct = ((mA >> 1) & 1) ? 0x3232u : 0x1010u;
                uint32_t sv;
                asm("prmt.b32 %0, %1, %1, %2;" : "=r"(sv) : "r"(w), "r"(ct));
                #pragma unroll
                for (int i = 0; i < 32; i++) t[i] = hmul2(xh[i], sv);
            }

            /* drain previous chunk's stores, then publish A(j-1) */
            asm volatile("tcgen05.wait::st.sync.aligned;" ::: "memory");
            asm volatile("tcgen05.fence::before_thread_sync;" ::: "memory");
            if (j > 0 && lane_elect) {
                if (bgate) {
                    /* W tiles needed by chunk j-1: up to floor(3(j-1)/2)+1 */
                    int need = ((3 * (j - 1)) >> 1) + 1;
                    while (bt <= need) {
                        mbar_wait(base + SM_MB_B + (bt % W_RING) * 8, (uint32_t)((bt / W_RING) & 1));
                        bt++;
                    }
                }
                asm volatile("mbarrier.arrive.shared.b64 _, [%0];"
                             :: "r"(base + SM_MB_A + ((j - 1) & 1) * 8) : "memory");
            }

            /* store first sub-block */
            sttm_x32(abase + (uint32_t)(sA * 32), t);

            /* second owned sub-block (s=2) for the 'two' group */
            if (two) {
                int m2 = 3 * j + 2;
                if (m2 == 128) {
                    /* bias block: A[e,k] = fp16(vert[e,k]), k in [0,64) */
                    #pragma unroll
                    for (int i = 0; i < 32; i++) t[i] = lds32(vrow + (uint32_t)(i * 4));
                } else {
                    uint32_t w  = lds32(vrow + (uint32_t)((m2 >> 2) << 2));
                    uint32_t ct = ((m2 >> 1) & 1) ? 0x3232u : 0x1010u;
                    uint32_t sv;
                    asm("prmt.b32 %0, %1, %1, %2;" : "=r"(sv) : "r"(w), "r"(ct));
                    #pragma unroll
                    for (int i = 0; i < 32; i++) t[i] = hmul2(xh[i], sv);
                }
                sttm_x32(abase + 64u, t);
            }
        }
        /* publish final chunk A(42): slot 0 */
        asm volatile("tcgen05.wait::st.sync.aligned;" ::: "memory");
        asm volatile("tcgen05.fence::before_thread_sync;" ::: "memory");
        if (lane_elect) {
            if (bgate) {
                int need = ((3 * (NCHUNK - 1)) >> 1) + 1;   /* 64 */
                while (bt <= need) {
                    mbar_wait(base + SM_MB_B + (bt % W_RING) * 8, (uint32_t)((bt / W_RING) & 1));
                    bt++;
                }
            }
            asm volatile("mbarrier.arrive.shared.b64 _, [%0];"
                         :: "r"(base + SM_MB_A + LAST_S * 8) : "memory");
        }
    } else if (is_issuer) {
        /* ---------------- dedicated MMA-issuer thread ---------------- */
        for (int j = 0; j < NCHUNK; j++) {
            /* A(j) written AND all W tiles for chunk j resident */
            mbar_wait(base + SM_MB_A + (j & 1) * 8, (uint32_t)((j >> 1) & 1));
            asm volatile("tcgen05.fence::after_thread_sync;" ::: "memory");

            const uint32_t aMma = tmem + TM_A + (uint32_t)(j & 1) * 96u;
            #pragma unroll
            for (int s = 0; s < 3; s++) {
                const int m    = 3 * j + s;
                const int wtile = m >> 1;
                const uint32_t wslot = (uint32_t)(wtile % W_RING);
                const uint64_t bdesc = (DBASE |
                    ((uint64_t)((base + SM_B + wslot * B_TILE) >> 4) & 0x3FFFull))
                    + (uint64_t)((m & 1) * 512);
                #pragma unroll
                for (int kk = 0; kk < 4; kk++) {
                    uint64_t bd = bdesc + (uint64_t)(kk * 2);
                    uint32_t at = aMma + (uint32_t)(s * 32 + kk * 8);
                    uint32_t en = ((j > 0) || (s > 0) || (kk > 0)) ? 1u : 0u;
                    asm volatile(
                        "{\n\t.reg .pred p;\n\tsetp.ne.u32 p, %5, 0;\n\t"
                        "tcgen05.mma.cta_group::1.kind::f16 [%0], [%1], %2, %3, {%4, %4, %4, %4}, p;\n\t}"
                        :: "r"(tmem + TM_D), "r"(at), "l"(bd), "r"(0x08100010u), "r"(0u), "r"(en)
                        : "memory");
                }
            }
            asm volatile("tcgen05.commit.cta_group::1.mbarrier::arrive::one.shared::cluster.b64 [%0];"
                         :: "r"(base + SM_MB_D + (j & 1) * 8) : "memory");
        }
    }

    /* wait for last chunk's MMAs (j=42: slot 0, parity 1) */
    mbar_wait(base + SM_MB_D + LAST_S * 8, (uint32_t)LAST_P);
    asm volatile("tcgen05.fence::after_thread_sync;" ::: "memory");

    if (wid < 4) {
        uint32_t d[64];
        #pragma unroll
        for (int hb = 0; hb < 2; hb++) {
            uint32_t* rr = d + hb * 32;
            asm volatile(
                "tcgen05.ld.sync.aligned.32x32b.x32.b32 "
                "{%0, %1, %2, %3, %4, %5, %6, %7, "
                " %8, %9, %10, %11, %12, %13, %14, %15, "
                " %16, %17, %18, %19, %20, %21, %22, %23, "
                " %24, %25, %26, %27, %28, %29, %30, %31}, [%32];"
                : "=r"(rr[0]),  "=r"(rr[1]),  "=r"(rr[2]),  "=r"(rr[3]),
                  "=r"(rr[4]),  "=r"(rr[5]),  "=r"(rr[6]),  "=r"(rr[7]),
                  "=r"(rr[8]),  "=r"(rr[9]),  "=r"(rr[10]), "=r"(rr[11]),
                  "=r"(rr[12]), "=r"(rr[13]), "=r"(rr[14]), "=r"(rr[15]),
                  "=r"(rr[16]), "=r"(rr[17]), "=r"(rr[18]), "=r"(rr[19]),
                  "=r"(rr[20]), "=r"(rr[21]), "=r"(rr[22]), "=r"(rr[23]),
                  "=r"(rr[24]), "=r"(rr[25]), "=r"(rr[26]), "=r"(rr[27]),
                  "=r"(rr[28]), "=r"(rr[29]), "=r"(rr[30]), "=r"(rr[31])
                : "r"(tmem + TM_D + hb * 32));
        }
        asm volatile("tcgen05.wait::ld.sync.aligned;" ::: "memory");
        int eo = tb + wid * 32 + lane;
        if (eo < E_TOT) {
            float4* dst = (float4*)(out + (size_t)eo * 64);
            #pragma unroll
            for (int c4 = 0; c4 < 16; c4++) {
                float4 v;
                v.x = __uint_as_float(d[c4 * 4 + 0]);
                v.y = __uint_as_float(d[c4 * 4 + 1]);
                v.z = __uint_as_float(d[c4 * 4 + 2]);
                v.w = __uint_as_float(d[c4 * 4 + 3]);
                dst[c4] = v;
            }
        }
    }
    __syncthreads();
    if (wid == 0) {
        asm volatile("tcgen05.dealloc.cta_group::1.sync.aligned.b32 %0, 256;" :: "r"(tmem));
    }

#else
    /* ================= fallback path (plain sm_103; compile-only on this target,
       the sm_103a SASS is always selected at load time on GB300) ================= */
    float* Xs  = (float*)(sb + FB_X);
    float* Vs  = (float*)(sb + FB_V);
    float* Bs  = (float*)(sb + FB_B);
    float* Bsm = (float*)(sb + FB_S);

    for (int i = tid; i < 128 * 128; i += NTHREADS) {
        int e2 = i >> 7, k = i & 127;
        int ge = tb + e2; if (ge >= E_TOT) ge = E_TOT - 1;
        Xs[k * 132 + e2] = xedges[(size_t)ge * 128 + k];
    }
    for (int i = tid; i < 128 * 64; i += NTHREADS) {
        int e2 = i >> 6, v = i & 63;
        int ge = tb + e2; if (ge >= E_TOT) ge = E_TOT - 1;
        Vs[v * 132 + e2] = vert[(size_t)ge * 64 + v];
    }
    for (int i = tid; i < 4096; i += NTHREADS) {
        int v = i & 63, m = i >> 6;
        Bsm[v * 64 + m] = bg[m * 64 + v];
    }

    const int ebk = tid & 31;
    const int mb  = tid >> 5;
    float acc[4][8];
    #pragma unroll
    for (int i = 0; i < 4; i++)
        #pragma unroll
        for (int jj = 0; jj < 8; jj++) acc[i][jj] = 0.f;

    auto issueW = [&](int v, int buf) {
        uint32_t dbase = base + FB_B + (uint32_t)buf * 33792u;
        for (int c = tid; c < 2048; c += NTHREADS) {
            int m = c >> 5, k4 = c & 31;
            const float* src = Wg + ((size_t)(m * 64 + v)) * 128 + k4 * 4;
            uint32_t dst = dbase + (uint32_t)(m * 528 + k4 * 16);
            asm volatile("cp.async.ca.shared.global [%0], [%1], 16;" :: "r"(dst), "l"(src) : "memory");
        }
        asm volatile("cp.async.commit_group;" ::: "memory");
    };

    issueW(0, 0);
    __syncthreads();

    for (int v = 0; v < 64; v++) {
        int buf = v & 1;
        if (v + 1 < 64) {
            issueW(v + 1, buf ^ 1);
            asm volatile("cp.async.wait_group 1;" ::: "memory");
        } else {
            asm volatile("cp.async.wait_group 0;" ::: "memory");
        }
        __syncthreads();

        if (tid < 256) {
            float4 vsv = *(const float4*)(Vs + v * 132 + ebk * 4);
            const float* Bv = Bs + (size_t)buf * 8448 + (size_t)mb * 8 * 132;

            for (int k = 0; k < 128; k++) {
                float4 x4 = *(const float4*)(Xs + k * 132 + ebk * 4);
                float xa0 = x4.x * vsv.x, xa1 = x4.y * vsv.y;
                float xa2 = x4.z * vsv.z, xa3 = x4.w * vsv.w;
                #pragma unroll
                for (int jj = 0; jj < 8; jj++) {
                    float bvj = Bv[jj * 132 + k];
                    acc[0][jj] += xa0 * bvj;
                    acc[1][jj] += xa1 * bvj;
                    acc[2][jj] += xa2 * bvj;
                    acc[3][jj] += xa3 * bvj;
                }
            }
        }
        __syncthreads();
    }

    if (tid < 256) {
        for (int v = 0; v < 64; v++) {
            float4 vsv = *(const float4*)(Vs + v * 132 + ebk * 4);
            #pragma unroll
            for (int jj = 0; jj < 8; jj++) {
                float bb = Bsm[v * 64 + mb * 8 + jj];
                acc[0][jj] += vsv.x * bb;
                acc[1][jj] += vsv.y * bb;
                acc[2][jj] += vsv.z * bb;
                acc[3][jj] += vsv.w * bb;
            }
        }

        #pragma unroll
        for (int i = 0; i < 4; i++) {
            int e2 = tb + ebk * 4 + i;
            if (e2 < E_TOT) {
                #pragma unroll
                for (int jj = 0; jj < 8; jj++)
                    out[(size_t)e2 * 64 + mb * 8 + jj] = acc[i][jj];
            }
        }
    }
#endif
}

/* ---------------- launcher ---------------- */
extern "C" void kernel_launch(void* const* d_in, const int* in_sizes, int n_in,
                              void* d_out, int out_size) {
    const float* vert  = (const float*)d_in[0];  /* [100000, 64]  */
    const float* edges = (const float*)d_in[1];  /* [100000, 128] */
    const float* W     = (const float*)d_in[2];  /* [4096, 128]   */
    const float* b     = (const float*)d_in[3];  /* [4096]        */
    float* out = (float*)d_out;                  /* [100000, 64]  */

    prep_w<<<1040, 256>>>(W, b);

    cudaFuncSetAttribute(edge_msg_main, cudaFuncAttributeMaxDynamicSharedMemorySize, SMEM_DYN);
    edge_msg_main<<<NTILES, NTHREADS, SMEM_DYN>>>(vert, edges, W, b, out);
}

// round 17
// speedup vs baseline: 1.3368x; 1.3368x over previous
#include <cuda_runtime.h>
#include <cuda_fp16.h>
#include <cstdint>

#define E_TOT      100000
#define NCHUNK     65
#define B_TILE     16384
#define NTILES     782          /* ceil(100000/128) */
#define NTHREADS   288          /* 8 producer warps + 1 issuer warp */

/* ---- tcgen05-path smem layout (relative to 1024-aligned base) ---- */
#define SM_B       0            /* 4 x 16384 = 65536 : W ring (TMA)    */
#define SM_V       65536        /* 128 rows x 132 B fp16 vert = 16896  */
#define SM_TPTR    82432
#define SM_MB_D    82448        /* 3 x 8B : mma committed (A-buf gate) */
#define SM_MB_A    82472        /* 3 x 8B : A-buf full (count 8)       */
#define SM_MB_B    82496        /* 4 x 8B : W-chunk full (TMA)         */
#define SM_END     82528

#define SMEM_DYN   (SM_END + 1024)   /* ~83.5KB/CTA -> 2 CTAs/SM */

/* TMEM column map (alloc 256): D = [0,64), A bufs at 64 / 128 / 192 */
#define TM_D       0
#define TM_A       64

/* last chunk j=64: D slot 64%3=1, parity (64/3)&1=1 */
#define LAST_S     1
#define LAST_P     1

/* ---- fallback-path smem layout (compile-only on plain sm_103 pass) ---- */
#define FB_X       0
#define FB_V       67584
#define FB_B       101376
#define FB_S       168960

/* does this device pass have tcgen05 (arch-specific sm_103a/sm_100a)? */
#if !defined(__CUDA_ARCH__)
#  define TCPATH 1   /* host pass: parse the tcgen05 branch (not codegen'd) */
#elif defined(__CUDA_ARCH_FEAT_SM103_ALL) || defined(__CUDA_ARCH_FEAT_SM100_ALL) || \
      defined(__CUDA_ARCH_FEAT_SM101_ALL) || defined(__CUDA_ARCH_SPECIFIC__)
#  define TCPATH 1
#else
#  define TCPATH 0
#endif

/* pre-swizzled fp16 W' image: 65 chunks of [64 n x 128 k] blocked SW128 */
__device__ __align__(16) unsigned char g_Wimg[NCHUNK * B_TILE];

/* ---------------- generic helpers ---------------- */

__device__ __forceinline__ uint32_t sw128(uint32_t x) { return x ^ ((x >> 3) & 0x70u); }

__device__ __forceinline__ uint32_t smem_u32(const void* p) {
    uint32_t a;
    asm("{ .reg .u64 t; cvta.to.shared.u64 t, %1; cvt.u32.u64 %0, t; }" : "=r"(a) : "l"(p));
    return a;
}

/* pack two f32 -> f16x2; 'lo' lands in the low (memory-first) half */
__device__ __forceinline__ uint32_t pack_h2(float lo, float hi) {
    uint32_t r;
    asm("cvt.rn.f16x2.f32 %0, %1, %2;" : "=r"(r) : "f"(hi), "f"(lo));
    return r;
}

__device__ __forceinline__ uint32_t hmul2(uint32_t a, uint32_t b) {
    uint32_t r;
    asm("mul.rn.f16x2 %0, %1, %2;" : "=r"(r) : "r"(a), "r"(b));
    return r;
}

__device__ __forceinline__ void sts32(uint32_t addr, uint32_t a) {
    asm volatile("st.shared.b32 [%0], %1;" :: "r"(addr), "r"(a) : "memory");
}
__device__ __forceinline__ uint32_t lds32(uint32_t addr) {
    uint32_t v;
    asm volatile("ld.shared.b32 %0, [%1];" : "=r"(v) : "r"(addr));
    return v;
}

__device__ __forceinline__ void mbar_wait(uint32_t mbar, uint32_t parity) {
    asm volatile(
        "{\n\t.reg .pred P;\n\tWL_%=:\n\t"
        "mbarrier.try_wait.parity.acquire.cta.shared::cta.b64 P, [%0], %1, 0x989680;\n\t"
        "@P bra.uni WD_%=;\n\tbra.uni WL_%=;\n\tWD_%=:\n\t}"
        :: "r"(mbar), "r"(parity) : "memory");
}

/* relaxed variant: ONLY for waits whose post-wait accesses to the protected
   data are async-proxy (tcgen05.st / TMA); tcgen05.fence::after follows. */
__device__ __forceinline__ void mbar_wait_relaxed(uint32_t mbar, uint32_t parity) {
    asm volatile(
        "{\n\t.reg .pred P;\n\tWL_%=:\n\t"
        "mbarrier.try_wait.parity.relaxed.cta.shared::cta.b64 P, [%0], %1, 0x989680;\n\t"
        "@P bra.uni WD_%=;\n\tbra.uni WL_%=;\n\tWD_%=:\n\t}"
        :: "r"(mbar), "r"(parity) : "memory");
}

#if TCPATH
/* store 32 b32 to 32 consecutive TMEM columns (warp-collective) */
__device__ __forceinline__ void sttm_x32(uint32_t addr, const uint32_t* t) {
    asm volatile(
        "tcgen05.st.sync.aligned.32x32b.x32.b32 [%0], "
        "{%1, %2, %3, %4, %5, %6, %7, %8, "
        " %9, %10, %11, %12, %13, %14, %15, %16, "
        " %17, %18, %19, %20, %21, %22, %23, %24, "
        " %25, %26, %27, %28, %29, %30, %31, %32};"
        :: "r"(addr),
           "r"(t[0]),  "r"(t[1]),  "r"(t[2]),  "r"(t[3]),
           "r"(t[4]),  "r"(t[5]),  "r"(t[6]),  "r"(t[7]),
           "r"(t[8]),  "r"(t[9]),  "r"(t[10]), "r"(t[11]),
           "r"(t[12]), "r"(t[13]), "r"(t[14]), "r"(t[15]),
           "r"(t[16]), "r"(t[17]), "r"(t[18]), "r"(t[19]),
           "r"(t[20]), "r"(t[21]), "r"(t[22]), "r"(t[23]),
           "r"(t[24]), "r"(t[25]), "r"(t[26]), "r"(t[27]),
           "r"(t[28]), "r"(t[29]), "r"(t[30]), "r"(t[31])
        : "memory");
}

__device__ __forceinline__ void tma_w(uint32_t dst, const unsigned char* src, uint32_t mbar) {
    asm volatile("mbarrier.arrive.expect_tx.shared.b64 _, [%0], %1;"
                 :: "r"(mbar), "r"((uint32_t)B_TILE) : "memory");
    asm volatile("cp.async.bulk.shared::cta.global.mbarrier::complete_tx::bytes [%0], [%1], %2, [%3];"
                 :: "r"(dst), "l"(src), "r"((uint32_t)B_TILE), "r"(mbar) : "memory");
}
#endif

/* ---------------- prep kernel: pre-swizzled fp16 W' image ---------------- */
/* chunk c<64: Wc[n,k] = W[n*64+c, k]; chunk 64: Wc[n,k] = (k<64)? b[n*64+k] : 0 */
__global__ void prep_w(const float* __restrict__ W, const float* __restrict__ b) {
    uint32_t gid = blockIdx.x * 256u + threadIdx.x;      /* 0 .. 266239 */
    uint32_t c  = gid >> 12;
    uint32_t r  = gid & 4095u;
    uint32_t n  = r >> 6;
    uint32_t k  = (r & 63u) * 2u;
    float w0, w1;
    if (c < 64u) {
        const float* s = W + ((n * 64u + c) * 128u + k);
        w0 = s[0]; w1 = s[1];
    } else if (k < 64u) {
        w0 = b[n * 64u + k]; w1 = b[n * 64u + k + 1u];
    } else {
        w0 = 0.f; w1 = 0.f;
    }
    uint32_t off = ((n >> 3) + (k >> 6) * 8u) * 1024u + (n & 7u) * 128u + (k & 63u) * 2u;
    *(uint32_t*)(g_Wimg + c * B_TILE + sw128(off)) = pack_h2(w0, w1);
}

/* ---------------- main kernel ---------------- */
__global__ void __launch_bounds__(NTHREADS, 2)
edge_msg_main(const float* __restrict__ vert,
              const float* __restrict__ xedges,
              const float* __restrict__ Wg,
              const float* __restrict__ bg,
              float* __restrict__ out)
{
    extern __shared__ unsigned char smem_raw[];
    const uint32_t raw  = smem_u32(smem_raw);
    const uint32_t base = (raw + 1023u) & ~1023u;
    unsigned char* sb   = smem_raw + (base - raw);

    const int tid  = threadIdx.x;
    const int tb   = blockIdx.x * 128;

#if TCPATH
    /* ========== tcgen05 path: TS-mode A in TMEM, TMA W ring (depth 4),
       single STTM.x32/chunk, deferred wait::st, warp-7-only B-wait,
       warp-6 W refills (gate free via its own D-gate), lean issuer ===== */
    const int wid    = tid >> 5;
    const int lane   = tid & 31;
    const bool prod  = (tid < 256);
    const int wg     = (tid >> 7) & 1; /* producers: K-half owner */
    const int wg_tid = tid & 127;
    const int r      = wg_tid;         /* owned A row (M index) */

    (void)Wg; (void)bg; (void)sb;

    if (tid == 0) {
        #pragma unroll
        for (int i = 0; i < 3; i++) {
            asm volatile("mbarrier.init.shared.b64 [%0], 1;" :: "r"(base + SM_MB_D + i * 8) : "memory");
            asm volatile("mbarrier.init.shared.b64 [%0], 8;" :: "r"(base + SM_MB_A + i * 8) : "memory");
        }
        #pragma unroll
        for (int i = 0; i < 4; i++)
            asm volatile("mbarrier.init.shared.b64 [%0], 1;" :: "r"(base + SM_MB_B + i * 8) : "memory");
    }
    if (wid == 0) {
        asm volatile("tcgen05.alloc.cta_group::1.sync.aligned.shared::cta.b32 [%0], 256;"
                     :: "r"(base + SM_TPTR) : "memory");
        asm volatile("tcgen05.relinquish_alloc_permit.cta_group::1.sync.aligned;");
    }
    __syncthreads();
    uint32_t tmem;
    asm volatile("ld.shared.b32 %0, [%1];" : "=r"(tmem) : "r"(base + SM_TPTR));

    bool lane_elect = false;   /* one thread per warp */
    {
        uint32_t p;
        asm volatile("{\n\t.reg .pred P;\n\telect.sync _|P, 0xFFFFFFFF;\n\tselp.b32 %0, 1, 0, P;\n\t}" : "=r"(p));
        lane_elect = (p != 0);
    }
    const bool is_issuer = (wid == 8) && lane_elect;
    const bool bgate     = (wid == 7);   /* producer warp that gates on W residency */
    const bool wfill     = (wid == 6);   /* producer warp that issues W refills     */

    /* prefetch W chunks 0,1 via TMA (issuer) */
    if (is_issuer) {
        tma_w(base + SM_B + 0 * B_TILE, g_Wimg + (size_t)0 * B_TILE, base + SM_MB_B + 0 * 8);
        tma_w(base + SM_B + 1 * B_TILE, g_Wimg + (size_t)1 * B_TILE, base + SM_MB_B + 1 * 8);
    }

    int e = tb + r; if (e >= E_TOT) e = E_TOT - 1;

    /* producers: stage vertices as fp16 (row stride 132 B) + edge half-row regs */
    const uint32_t vb    = base + SM_V;
    const uint32_t vrow  = vb + (uint32_t)(r * 132);
    uint32_t xh[32];
    uint32_t aTBase = 0;
    if (prod) {
        const float4* vp = (const float4*)(vert + (size_t)e * 64 + wg * 32);
        uint32_t dst = vrow + (uint32_t)(wg * 64);
        #pragma unroll
        for (int i = 0; i < 8; i++) {
            float4 v = vp[i];
            sts32(dst + (uint32_t)(i * 8),     pack_h2(v.x, v.y));
            sts32(dst + (uint32_t)(i * 8 + 4), pack_h2(v.z, v.w));
        }
        const float4* xp = (const float4*)(xedges + (size_t)e * 128 + wg * 64);
        #pragma unroll
        for (int i = 0; i < 16; i++) {
            float4 v = xp[i];
            xh[i * 2 + 0] = pack_h2(v.x, v.y);
            xh[i * 2 + 1] = pack_h2(v.z, v.w);
        }
        aTBase = tmem + TM_A + (uint32_t)(wg * 32) + (((uint32_t)(wg_tid >> 5)) << 21);
    }
    __syncthreads();   /* vertices staged, mbarriers live, TMEM ptr read */

    /* smem desc base: SW128, version=1, SBO=64, LBO=1 */
    const uint64_t DBASE = (uint64_t(2) << 61) | (uint64_t(1) << 46) |
                           (uint64_t(64) << 32) | (uint64_t(1) << 16);

    if (prod) {
        /* ---------------- producer warps ---------------- */
        int s3 = 0, p3 = 0;
        for (int j = 0; j < NCHUNK; j++) {
            const uint32_t abuf = (uint32_t)s3 * 64u;

            /* A-buf reuse gate: commit of chunk j-3 (post-wait protected accesses
               are async-proxy only -> relaxed wait + tcgen05 fence) */
            if (j >= 3) {
                mbar_wait_relaxed(base + SM_MB_D + s3 * 8, (uint32_t)(p3 ^ 1));
                asm volatile("tcgen05.fence::after_thread_sync;" ::: "memory");
            }

            /* warp 6: refill W(j+1) into slot (j+1)&3.
               Slot previously held W(j-3); reader MMA(j-3) completion is
               exactly what this warp's D-gate above guarantees (j>=3).
               For j=1,2 the slots are untouched since the prologue. */
            if (wfill && lane_elect && j >= 1 && j + 1 < NCHUNK) {
                uint32_t ws = (uint32_t)((j + 1) & 3);
                tma_w(base + SM_B + ws * B_TILE,
                      g_Wimg + (size_t)(j + 1) * B_TILE,
                      base + SM_MB_B + ws * 8);
            }

            /* compute all of A(j) while STTM(j-1) drains */
            uint32_t t[32];
            if (j < 64) {
                uint32_t w  = lds32(vrow + (uint32_t)((j >> 1) << 2));
                uint32_t ct = (j & 1) ? 0x3232u : 0x1010u;
                uint32_t sv;
                asm("prmt.b32 %0, %1, %1, %2;" : "=r"(sv) : "r"(w), "r"(ct));
                #pragma unroll
                for (int i = 0; i < 32; i++) t[i] = hmul2(xh[i], sv);
            } else {
                /* bias chunk: A[e,k] = (k<64)? fp16(vert[e,k]) : 0 */
                if (wg == 0) {
                    #pragma unroll
                    for (int i = 0; i < 32; i++) t[i] = lds32(vrow + (uint32_t)(i * 4));
                } else {
                    #pragma unroll
                    for (int i = 0; i < 32; i++) t[i] = 0u;
                }
            }

            /* drain previous chunk's stores, then publish A(j-1) */
            asm volatile("tcgen05.wait::st.sync.aligned;" ::: "memory");
            asm volatile("tcgen05.fence::before_thread_sync;" ::: "memory");
            if (j > 0 && lane_elect) {
                if (bgate) {
                    /* fold W(j-1)-residency into warp 7's arrive: A-full
                       then implies B-ready for the issuer */
                    int pc = j - 1;
                    mbar_wait(base + SM_MB_B + (pc & 3) * 8, (uint32_t)((pc >> 2) & 1));
                }
                int ps = (s3 == 0) ? 2 : s3 - 1;
                asm volatile("mbarrier.arrive.shared.b64 _, [%0];"
                             :: "r"(base + SM_MB_A + ps * 8) : "memory");
            }

            /* store A(j): one x32 transaction */
            sttm_x32(aTBase + abuf, t);

            if (++s3 == 3) { s3 = 0; p3 ^= 1; }
        }
        /* publish final chunk A(64): slot 1 */
        asm volatile("tcgen05.wait::st.sync.aligned;" ::: "memory");
        asm volatile("tcgen05.fence::before_thread_sync;" ::: "memory");
        if (lane_elect) {
            if (bgate)
                mbar_wait(base + SM_MB_B + (64 & 3) * 8, (uint32_t)((64 >> 2) & 1));
            asm volatile("mbarrier.arrive.shared.b64 _, [%0];"
                         :: "r"(base + SM_MB_A + 1 * 8) : "memory");
        }
    } else if (is_issuer) {
        /* ---------------- dedicated MMA-issuer thread (minimal loop) -------- */
        int s3 = 0, p3 = 0;
        for (int j = 0; j < NCHUNK; j++) {
            /* A(j) written AND W(j) resident (warp 7 gated its arrive) */
            mbar_wait(base + SM_MB_A + s3 * 8, (uint32_t)p3);
            asm volatile("tcgen05.fence::after_thread_sync;" ::: "memory");

            const int s4 = j & 3;
            const uint64_t bdesc = DBASE |
                ((uint64_t)((base + SM_B + (uint32_t)s4 * B_TILE) >> 4) & 0x3FFFull);
            const uint32_t aMma = tmem + TM_A + (uint32_t)s3 * 64u;
            #pragma unroll
            for (int kk = 0; kk < 8; kk++) {
                uint64_t bd = bdesc + (uint64_t)((kk >> 2) * 512 + (kk & 3) * 2);
                uint32_t at = aMma + (uint32_t)(kk * 8);
                uint32_t en = ((j > 0) || (kk > 0)) ? 1u : 0u;
                asm volatile(
                    "{\n\t.reg .pred p;\n\tsetp.ne.u32 p, %5, 0;\n\t"
                    "tcgen05.mma.cta_group::1.kind::f16 [%0], [%1], %2, %3, {%4, %4, %4, %4}, p;\n\t}"
                    :: "r"(tmem + TM_D), "r"(at), "l"(bd), "r"(0x08100010u), "r"(0u), "r"(en)
                    : "memory");
            }
            asm volatile("tcgen05.commit.cta_group::1.mbarrier::arrive::one.shared::cluster.b64 [%0];"
                         :: "r"(base + SM_MB_D + s3 * 8) : "memory");

            if (++s3 == 3) { s3 = 0; p3 ^= 1; }
        }
    }

    /* wait for last chunk's MMAs (j=64: slot 1, parity 1) */
    mbar_wait(base + SM_MB_D + LAST_S * 8, (uint32_t)LAST_P);
    asm volatile("tcgen05.fence::after_thread_sync;" ::: "memory");

    if (wid < 4) {
        uint32_t d[64];
        #pragma unroll
        for (int hb = 0; hb < 2; hb++) {
            uint32_t* rr = d + hb * 32;
            asm volatile(
                "tcgen05.ld.sync.aligned.32x32b.x32.b32 "
                "{%0, %1, %2, %3, %4, %5, %6, %7, "
                " %8, %9, %10, %11, %12, %13, %14, %15, "
                " %16, %17, %18, %19, %20, %21, %22, %23, "
                " %24, %25, %26, %27, %28, %29, %30, %31}, [%32];"
                : "=r"(rr[0]),  "=r"(rr[1]),  "=r"(rr[2]),  "=r"(rr[3]),
                  "=r"(rr[4]),  "=r"(rr[5]),  "=r"(rr[6]),  "=r"(rr[7]),
                  "=r"(rr[8]),  "=r"(rr[9]),  "=r"(rr[10]), "=r"(rr[11]),
                  "=r"(rr[12]), "=r"(rr[13]), "=r"(rr[14]), "=r"(rr[15]),
                  "=r"(rr[16]), "=r"(rr[17]), "=r"(rr[18]), "=r"(rr[19]),
                  "=r"(rr[20]), "=r"(rr[21]), "=r"(rr[22]), "=r"(rr[23]),
                  "=r"(rr[24]), "=r"(rr[25]), "=r"(rr[26]), "=r"(rr[27]),
                  "=r"(rr[28]), "=r"(rr[29]), "=r"(rr[30]), "=r"(rr[31])
                : "r"(tmem + TM_D + hb * 32));
        }
        asm volatile("tcgen05.wait::ld.sync.aligned;" ::: "memory");
        int eo = tb + wid * 32 + lane;
        if (eo < E_TOT) {
            float4* dst = (float4*)(out + (size_t)eo * 64);
            #pragma unroll
            for (int c4 = 0; c4 < 16; c4++) {
                float4 v;
                v.x = __uint_as_float(d[c4 * 4 + 0]);
                v.y = __uint_as_float(d[c4 * 4 + 1]);
                v.z = __uint_as_float(d[c4 * 4 + 2]);
                v.w = __uint_as_float(d[c4 * 4 + 3]);
                dst[c4] = v;
            }
        }
    }
    __syncthreads();
    if (wid == 0) {
        asm volatile("tcgen05.dealloc.cta_group::1.sync.aligned.b32 %0, 256;" :: "r"(tmem));
    }

#else
    /* ================= fallback path (plain sm_103; compile-only on this target,
       the sm_103a SASS is always selected at load time on GB300) ================= */
    float* Xs  = (float*)(sb + FB_X);
    float* Vs  = (float*)(sb + FB_V);
    float* Bs  = (float*)(sb + FB_B);
    float* Bsm = (float*)(sb + FB_S);

    for (int i = tid; i < 128 * 128; i += NTHREADS) {
        int e2 = i >> 7, k = i & 127;
        int ge = tb + e2; if (ge >= E_TOT) ge = E_TOT - 1;
        Xs[k * 132 + e2] = xedges[(size_t)ge * 128 + k];
    }
    for (int i = tid; i < 128 * 64; i += NTHREADS) {
        int e2 = i >> 6, v = i & 63;
        int ge = tb + e2; if (ge >= E_TOT) ge = E_TOT - 1;
        Vs[v * 132 + e2] = vert[(size_t)ge * 64 + v];
    }
    for (int i = tid; i < 4096; i += NTHREADS) {
        int v = i & 63, m = i >> 6;
        Bsm[v * 64 + m] = bg[m * 64 + v];
    }

    const int ebk = tid & 31;
    const int mb  = tid >> 5;
    float acc[4][8];
    #pragma unroll
    for (int i = 0; i < 4; i++)
        #pragma unroll
        for (int jj = 0; jj < 8; jj++) acc[i][jj] = 0.f;

    auto issueW = [&](int v, int buf) {
        uint32_t dbase = base + FB_B + (uint32_t)buf * 33792u;
        for (int c = tid; c < 2048; c += NTHREADS) {
            int m = c >> 5, k4 = c & 31;
            const float* src = Wg + ((size_t)(m * 64 + v)) * 128 + k4 * 4;
            uint32_t dst = dbase + (uint32_t)(m * 528 + k4 * 16);
            asm volatile("cp.async.ca.shared.global [%0], [%1], 16;" :: "r"(dst), "l"(src) : "memory");
        }
        asm volatile("cp.async.commit_group;" ::: "memory");
    };

    issueW(0, 0);
    __syncthreads();

    for (int v = 0; v < 64; v++) {
        int buf = v & 1;
        if (v + 1 < 64) {
            issueW(v + 1, buf ^ 1);
            asm volatile("cp.async.wait_group 1;" ::: "memory");
        } else {
            asm volatile("cp.async.wait_group 0;" ::: "memory");
        }
        __syncthreads();

        if (tid < 256) {
            float4 vsv = *(const float4*)(Vs + v * 132 + ebk * 4);
            const float* Bv = Bs + (size_t)buf * 8448 + (size_t)mb * 8 * 132;

            for (int k = 0; k < 128; k++) {
                float4 x4 = *(const float4*)(Xs + k * 132 + ebk * 4);
                float xa0 = x4.x * vsv.x, xa1 = x4.y * vsv.y;
                float xa2 = x4.z * vsv.z, xa3 = x4.w * vsv.w;
                #pragma unroll
                for (int jj = 0; jj < 8; jj++) {
                    float bvj = Bv[jj * 132 + k];
                    acc[0][jj] += xa0 * bvj;
                    acc[1][jj] += xa1 * bvj;
                    acc[2][jj] += xa2 * bvj;
                    acc[3][jj] += xa3 * bvj;
                }
            }
        }
        __syncthreads();
    }

    if (tid < 256) {
        for (int v = 0; v < 64; v++) {
            float4 vsv = *(const float4*)(Vs + v * 132 + ebk * 4);
            #pragma unroll
            for (int jj = 0; jj < 8; jj++) {
                float bb = Bsm[v * 64 + mb * 8 + jj];
                acc[0][jj] += vsv.x * bb;
                acc[1][jj] += vsv.y * bb;
                acc[2][jj] += vsv.z * bb;
                acc[3][jj] += vsv.w * bb;
            }
        }

        #pragma unroll
        for (int i = 0; i < 4; i++) {
            int e2 = tb + ebk * 4 + i;
            if (e2 < E_TOT) {
                #pragma unroll
                for (int jj = 0; jj < 8; jj++)
                    out[(size_t)e2 * 64 + mb * 8 + jj] = acc[i][jj];
            }
        }
    }
#endif
}

/* ---------------- launcher ---------------- */
extern "C" void kernel_launch(void* const* d_in, const int* in_sizes, int n_in,
                              void* d_out, int out_size) {
    const float* vert  = (const float*)d_in[0];  /* [100000, 64]  */
    const float* edges = (const float*)d_in[1];  /* [100000, 128] */
    const float* W     = (const float*)d_in[2];  /* [4096, 128]   */
    const float* b     = (const float*)d_in[3];  /* [4096]        */
    float* out = (float*)d_out;                  /* [100000, 64]  */

    prep_w<<<1040, 256>>>(W, b);

    cudaFuncSetAttribute(edge_msg_main, cudaFuncAttributeMaxDynamicSharedMemorySize, SMEM_DYN);
    edge_msg_main<<<NTILES, NTHREADS, SMEM_DYN>>>(vert, edges, W, b, out);
}